// round 10
// baseline (speedup 1.0000x reference)
#include <cuda_runtime.h>

#define NB      4
#define RB      72          // NB * 18 rows per CTA
#define THREADS 256
#define TSTEPS  128
#define NNODE   18
#define DIMX    32
#define HIDN    64
#define STF     132         // feature-buffer row stride (floats), padded
#define STH     68          // hidden-state row stride
#define STX     36          // x-tile row stride
#define NBLK    128         // grid: 512 / NB
#define STS2    24          // St2 row stride in float2

typedef unsigned long long u64;

// ---------------- packed f32x2 helpers ----------------
__device__ __forceinline__ u64 pk2(float a, float b) {
    u64 r;
    asm("mov.b64 %0, {%1, %2};" : "=l"(r)
        : "r"(__float_as_uint(a)), "r"(__float_as_uint(b)));
    return r;
}
__device__ __forceinline__ float2 up2(u64 v) {
    unsigned lo, hi;
    asm("mov.b64 {%0, %1}, %2;" : "=r"(lo), "=r"(hi) : "l"(v));
    return make_float2(__uint_as_float(lo), __uint_as_float(hi));
}
__device__ __forceinline__ void fma2(u64 &d, u64 a, u64 b) {
    asm("fma.rn.f32x2 %0, %1, %2, %0;" : "+l"(d) : "l"(a), "l"(b));
}
__device__ __forceinline__ void add2(u64 &d, u64 a) {
    asm("add.rn.f32x2 %0, %0, %1;" : "+l"(d) : "l"(a));
}

__device__ __forceinline__ float sigm(float v) {
    return 1.f / (1.f + __expf(-v));
}
__device__ __forceinline__ float tanh_(float v) {
    float e = __expf(2.f * v);
    return 1.f - 2.f / (e + 1.f);
}

// ---------------- shared memory layout ----------------
struct __align__(16) Smem {
    float2 St2[2][NNODE * STS2]; // transposed supports, duplicated pairs
    float X[RB * STX];          // x tile for current t
    float hA[RB * STH];
    float hB[RB * STH];
    float Z[RB * STF];          // concat input (gate Z; becomes cand Z in-place)
    float Da[RB * STF];         // Chebyshev x1 (aliases reduce scratch when dead)
    float Db[RB * STF];         // Chebyshev x2
    float OUT[RB * STF];        // gate output; only u-half (cols 64..127) used
};
// sizeof = 206688 B  (<= 227 KB dyn-smem limit, 1 CTA/SM)

// ---------------- spmm (4 cols/thread): dst = S @ src  (or 2*S@src - Zsub) ----
__device__ __forceinline__ void spmm4(const float2* __restrict__ St,
                                      const float* __restrict__ src,
                                      float* __restrict__ dst,
                                      const float* __restrict__ zsub,
                                      int CC, int rbase, int bloc, int nlo,
                                      int c0)
{
    if (c0 >= CC) return;
    const float* srcb = src + bloc * NNODE * STF + c0;
    u64 a[18];
#pragma unroll
    for (int i = 0; i < 18; i++) a[i] = 0;
#pragma unroll 1
    for (int mm = 0; mm < NNODE; mm++) {
        ulonglong2 z = *(const ulonglong2*)(srcb + mm * STF);
        const float2* sp = St + mm * STS2 + nlo;
        ulonglong2 p01 = *(const ulonglong2*)(sp);
        ulonglong2 p23 = *(const ulonglong2*)(sp + 2);
        ulonglong2 p45 = *(const ulonglong2*)(sp + 4);
        ulonglong2 p67 = *(const ulonglong2*)(sp + 6);
        u64        p8  = *(const u64*)(sp + 8);
        fma2(a[0],  p01.x, z.x); fma2(a[1],  p01.x, z.y);
        fma2(a[2],  p01.y, z.x); fma2(a[3],  p01.y, z.y);
        fma2(a[4],  p23.x, z.x); fma2(a[5],  p23.x, z.y);
        fma2(a[6],  p23.y, z.x); fma2(a[7],  p23.y, z.y);
        fma2(a[8],  p45.x, z.x); fma2(a[9],  p45.x, z.y);
        fma2(a[10], p45.y, z.x); fma2(a[11], p45.y, z.y);
        fma2(a[12], p67.x, z.x); fma2(a[13], p67.x, z.y);
        fma2(a[14], p67.y, z.x); fma2(a[15], p67.y, z.y);
        fma2(a[16], p8,    z.x); fma2(a[17], p8,    z.y);
    }
#pragma unroll
    for (int i = 0; i < 9; i++) {
        float2 q0 = up2(a[2 * i]), q1 = up2(a[2 * i + 1]);
        float4 o;
        if (zsub) {
            float4 zz = *(const float4*)(zsub + (rbase + i) * STF + c0);
            o = make_float4(2.f * q0.x - zz.x, 2.f * q0.y - zz.y,
                            2.f * q1.x - zz.z, 2.f * q1.y - zz.w);
        } else {
            o = make_float4(q0.x, q0.y, q1.x, q1.y);
        }
        *(float4*)(dst + (rbase + i) * STF + c0) = o;
    }
}

// ---------------- W loaders ----------------
__device__ __forceinline__ void ldwg(const float* p, ulonglong2 w[8]) {
#pragma unroll
    for (int kk = 0; kk < 4; kk++) {
        w[2 * kk]     = __ldg((const ulonglong2*)(p + kk * 128));
        w[2 * kk + 1] = __ldg((const ulonglong2*)(p + kk * 128 + 4));
    }
}
__device__ __forceinline__ void ldwc(const float* p, ulonglong2 w[4]) {
#pragma unroll
    for (int kk = 0; kk < 4; kk++)
        w[kk] = __ldg((const ulonglong2*)(p + kk * 64));
}

// gate GEMM k-slice: 9 rows x 8 cols per thread (16 fma2 per feat LDS.128)
template<int CC>
__device__ __forceinline__ void gemm_gate(const float* __restrict__ feat,
                                          const float* __restrict__ W,
                                          int kbeg, int c8, int rbase,
                                          u64 acc[36])
{
    constexpr int G = CC / 8;   // 4-k groups in this k-half
    const float* wp = W + (size_t)kbeg * 128 + c8;
    ulonglong2 wc[8], wn[8];
    ldwg(wp, wc);
#pragma unroll 2
    for (int g = 0; g < G; g++) {
        if (g + 1 < G) ldwg(wp + (size_t)(g + 1) * 512, wn);
        const float* fp = feat + rbase * STF + kbeg + 4 * g;
#pragma unroll
        for (int i = 0; i < 9; i++) {
            float4 f = *(const float4*)(fp + i * STF);
            u64 f0 = pk2(f.x, f.x), f1 = pk2(f.y, f.y);
            u64 f2 = pk2(f.z, f.z), f3 = pk2(f.w, f.w);
            fma2(acc[4 * i + 0], f0, wc[0].x); fma2(acc[4 * i + 1], f0, wc[0].y);
            fma2(acc[4 * i + 2], f0, wc[1].x); fma2(acc[4 * i + 3], f0, wc[1].y);
            fma2(acc[4 * i + 0], f1, wc[2].x); fma2(acc[4 * i + 1], f1, wc[2].y);
            fma2(acc[4 * i + 2], f1, wc[3].x); fma2(acc[4 * i + 3], f1, wc[3].y);
            fma2(acc[4 * i + 0], f2, wc[4].x); fma2(acc[4 * i + 1], f2, wc[4].y);
            fma2(acc[4 * i + 2], f2, wc[5].x); fma2(acc[4 * i + 3], f2, wc[5].y);
            fma2(acc[4 * i + 0], f3, wc[6].x); fma2(acc[4 * i + 1], f3, wc[6].y);
            fma2(acc[4 * i + 2], f3, wc[7].x); fma2(acc[4 * i + 3], f3, wc[7].y);
        }
#pragma unroll
        for (int q = 0; q < 8; q++) wc[q] = wn[q];
    }
}

// cand GEMM k-slice: 9 rows x 4 cols per thread
template<int CC>
__device__ __forceinline__ void gemm_cand(const float* __restrict__ feat,
                                          const float* __restrict__ W,
                                          int kbeg, int c4, int rbase,
                                          u64 acc[18])
{
    constexpr int G = CC / 8;
    const float* wp = W + (size_t)kbeg * 64 + c4;
    ulonglong2 wc[4], wn[4];
    ldwc(wp, wc);
#pragma unroll 2
    for (int g = 0; g < G; g++) {
        if (g + 1 < G) ldwc(wp + (size_t)(g + 1) * 256, wn);
        const float* fp = feat + rbase * STF + kbeg + 4 * g;
#pragma unroll
        for (int i = 0; i < 9; i++) {
            float4 f = *(const float4*)(fp + i * STF);
            fma2(acc[2 * i],     pk2(f.x, f.x), wc[0].x);
            fma2(acc[2 * i + 1], pk2(f.x, f.x), wc[0].y);
            fma2(acc[2 * i],     pk2(f.y, f.y), wc[1].x);
            fma2(acc[2 * i + 1], pk2(f.y, f.y), wc[1].y);
            fma2(acc[2 * i],     pk2(f.z, f.z), wc[2].x);
            fma2(acc[2 * i + 1], pk2(f.z, f.z), wc[2].y);
            fma2(acc[2 * i],     pk2(f.w, f.w), wc[3].x);
            fma2(acc[2 * i + 1], pk2(f.w, f.w), wc[3].y);
        }
#pragma unroll
        for (int q = 0; q < 4; q++) wc[q] = wn[q];
    }
}

// ---------------- main persistent kernel ----------------
__global__ void __launch_bounds__(THREADS, 1)
dcrnn_kernel(const float* __restrict__ x,   const float* __restrict__ sup,
             const float* __restrict__ wg0, const float* __restrict__ bg0,
             const float* __restrict__ wc0, const float* __restrict__ bc0,
             const float* __restrict__ wg1, const float* __restrict__ bg1,
             const float* __restrict__ wc1, const float* __restrict__ bc1,
             const float* __restrict__ fcw, const float* __restrict__ fcb,
             float* __restrict__ out)
{
    extern __shared__ char smraw[];
    Smem& sm = *reinterpret_cast<Smem*>(smraw);

    const int tid   = threadIdx.x;
    const int bbase = blockIdx.x * NB;
    const int rowg  = tid & 7;            // 8 row groups of 9 rows
    const int colg  = (tid >> 3) & 15;    // 16 col groups
    const int khalf = tid >> 7;           // k-slice half
    const int c8    = 8 * colg;           // gate col base
    const int c4    = 4 * colg;           // cand col base
    const int c0    = 4 * colg + 64 * khalf;  // spmm col base (covers 0..124)
    const int rbase = rowg * 9;
    const int bloc  = rowg >> 1;          // local batch of this thread's rows
    const int nlo   = (rowg & 1) ? 12 : 0; // St2 lane base

    u64* const scr = (u64*)sm.Da;         // reduce scratch aliases Da (dead then)

    // init: transpose + duplicate supports into St2
    for (int i = tid; i < 2 * NNODE * NNODE; i += THREADS) {
        int s = i / (NNODE * NNODE);
        int rem = i - s * NNODE * NNODE;
        int n = rem / NNODE;              // row of S
        int m = rem - n * NNODE;          // col of S
        float v = sup[i];
        int lane = (n < 9) ? n : (12 + n - 9);
        sm.St2[s][m * STS2 + lane] = make_float2(v, v);
    }
    for (int i = tid; i < RB * STH; i += THREADS) { sm.hA[i] = 0.f; sm.hB[i] = 0.f; }
    __syncthreads();

    for (int t = 0; t < TSTEPS; t++) {
        // ---- load x tile: X[r][0:32] = x[b, t, n, :] ----
        for (int j = tid; j < RB * 8; j += THREADS) {
            int r = j >> 3, d4 = j & 7;
            int b = bbase + r / NNODE;
            int n = r - NNODE * (r / NNODE);
            float4 v = *(const float4*)(x +
                (((size_t)b * TSTEPS + t) * NNODE + n) * DIMX + 4 * d4);
            *(float4*)(sm.X + r * STX + 4 * d4) = v;
        }
        __syncthreads();

        for (int cell = 0; cell < 2; cell++) {
            const int CC  = cell ? 128 : 96;
            const int CCH = CC >> 1;
            const int kbeg = khalf * CCH;
            const int hoff = cell ? HIDN : DIMX;   // offset of h-region in Z
            const float* WG = cell ? wg1 : wg0;
            const float* BG = cell ? bg1 : bg0;
            const float* WC = cell ? wc1 : wc0;
            const float* BC = cell ? bc1 : bc0;
            float* H = cell ? sm.hB : sm.hA;       // this cell's own state

            // ============ gate Z build: Z = [input | H] ============
            if (cell == 0) {
                for (int j = tid; j < RB * 24; j += THREADS) {
                    int r = j / 24, c = 4 * (j - 24 * r);
                    float4 v = (c < DIMX)
                        ? *(const float4*)(sm.X + r * STX + c)
                        : *(const float4*)(sm.hA + r * STH + (c - DIMX));
                    *(float4*)(sm.Z + r * STF + c) = v;
                }
            } else {
                for (int j = tid; j < RB * 32; j += THREADS) {
                    int r = j >> 5, c = 4 * (j & 31);
                    float4 v = (c < HIDN)
                        ? *(const float4*)(sm.hA + r * STH + c)
                        : *(const float4*)(sm.hB + r * STH + (c - HIDN));
                    *(float4*)(sm.Z + r * STF + c) = v;
                }
            }
            __syncthreads();

            // ============ GATE dconv + fused cand-Z build ============
            {
                u64 ga[36];
#pragma unroll
                for (int q = 0; q < 36; q++) ga[q] = 0;
#pragma unroll 1
                for (int m = 0; m < 5; m++) {
                    const float* feat;
                    if (m == 0) feat = sm.Z;
                    else {
                        int s = (m - 1) >> 1;
                        int second = (m - 1) & 1;
                        const float* src = second ? sm.Da : sm.Z;
                        float* dst = second ? sm.Db : sm.Da;
                        spmm4(sm.St2[s], src, dst,
                              second ? sm.Z : (const float*)0,
                              CC, rbase, bloc, nlo, c0);
                        __syncthreads();
                        feat = dst;
                    }
                    if (cell) gemm_gate<128>(feat, WG + (size_t)m * 128 * 128,
                                             kbeg, c8, rbase, ga);
                    else      gemm_gate<96> (feat, WG + (size_t)m * 96 * 128,
                                             kbeg, c8, rbase, ga);
                }
                __syncthreads();              // gemm done; Da/Db dead
                if (khalf) {
                    u64* s = scr + (size_t)(tid - 128) * 36;
#pragma unroll
                    for (int q = 0; q < 36; q++) s[q] = ga[q];
                }
                __syncthreads();
                if (!khalf) {
                    const u64* s = scr + (size_t)tid * 36;
#pragma unroll
                    for (int q = 0; q < 36; q++) add2(ga[q], s[q]);
                    float4 b0 = *(const float4*)(BG + c8);
                    float4 b1 = *(const float4*)(BG + c8 + 4);
                    if (c8 < HIDN) {
                        // r-part: write Z[r][hoff+c] = sigm(.)*H_prev[r][c]
#pragma unroll
                        for (int i = 0; i < 9; i++) {
                            int r = rbase + i;
                            float2 q0 = up2(ga[4 * i]),     q1 = up2(ga[4 * i + 1]);
                            float2 q2 = up2(ga[4 * i + 2]), q3 = up2(ga[4 * i + 3]);
                            float4 h0 = *(const float4*)(H + r * STH + c8);
                            float4 h1 = *(const float4*)(H + r * STH + c8 + 4);
                            float4 o0 = make_float4(sigm(q0.x + b0.x) * h0.x,
                                                    sigm(q0.y + b0.y) * h0.y,
                                                    sigm(q1.x + b0.z) * h0.z,
                                                    sigm(q1.y + b0.w) * h0.w);
                            float4 o1 = make_float4(sigm(q2.x + b1.x) * h1.x,
                                                    sigm(q2.y + b1.y) * h1.y,
                                                    sigm(q3.x + b1.z) * h1.z,
                                                    sigm(q3.y + b1.w) * h1.w);
                            *(float4*)(sm.Z + r * STF + hoff + c8)     = o0;
                            *(float4*)(sm.Z + r * STF + hoff + c8 + 4) = o1;
                        }
                    } else {
                        // u-part: store to OUT cols 64..127
#pragma unroll
                        for (int i = 0; i < 9; i++) {
                            int r = rbase + i;
                            float2 q0 = up2(ga[4 * i]),     q1 = up2(ga[4 * i + 1]);
                            float2 q2 = up2(ga[4 * i + 2]), q3 = up2(ga[4 * i + 3]);
                            float4 o0 = make_float4(sigm(q0.x + b0.x), sigm(q0.y + b0.y),
                                                    sigm(q1.x + b0.z), sigm(q1.y + b0.w));
                            float4 o1 = make_float4(sigm(q2.x + b1.x), sigm(q2.y + b1.y),
                                                    sigm(q3.x + b1.z), sigm(q3.y + b1.w));
                            *(float4*)(sm.OUT + r * STF + c8)     = o0;
                            *(float4*)(sm.OUT + r * STF + c8 + 4) = o1;
                        }
                    }
                }
                // Z low cols (input part) are already correct from gate Z build
            }
            __syncthreads();

            // ============ CANDIDATE dconv + fused GRU update ============
            {
                u64 ca[18];
#pragma unroll
                for (int q = 0; q < 18; q++) ca[q] = 0;
#pragma unroll 1
                for (int m = 0; m < 5; m++) {
                    const float* feat;
                    if (m == 0) feat = sm.Z;
                    else {
                        int s = (m - 1) >> 1;
                        int second = (m - 1) & 1;
                        const float* src = second ? sm.Da : sm.Z;
                        float* dst = second ? sm.Db : sm.Da;
                        spmm4(sm.St2[s], src, dst,
                              second ? sm.Z : (const float*)0,
                              CC, rbase, bloc, nlo, c0);
                        __syncthreads();
                        feat = dst;
                    }
                    if (cell) gemm_cand<128>(feat, WC + (size_t)m * 128 * 64,
                                             kbeg, c4, rbase, ca);
                    else      gemm_cand<96> (feat, WC + (size_t)m * 96 * 64,
                                             kbeg, c4, rbase, ca);
                }
                __syncthreads();
                if (khalf) {
                    u64* s = scr + (size_t)(tid - 128) * 18;
#pragma unroll
                    for (int q = 0; q < 18; q++) s[q] = ca[q];
                }
                __syncthreads();
                if (!khalf) {
                    const u64* s = scr + (size_t)tid * 18;
#pragma unroll
                    for (int q = 0; q < 18; q++) add2(ca[q], s[q]);
                    float4 bv = *(const float4*)(BC + c4);
#pragma unroll
                    for (int i = 0; i < 9; i++) {
                        int r = rbase + i;
                        float2 q0 = up2(ca[2 * i]), q1 = up2(ca[2 * i + 1]);
                        float4 cc4 = make_float4(tanh_(q0.x + bv.x), tanh_(q0.y + bv.y),
                                                 tanh_(q1.x + bv.z), tanh_(q1.y + bv.w));
                        float4 uu = *(const float4*)(sm.OUT + r * STF + HIDN + c4);
                        float4 hh = *(const float4*)(H + r * STH + c4);
                        float4 nh = make_float4(cc4.x + uu.x * (hh.x - cc4.x),
                                                cc4.y + uu.y * (hh.y - cc4.y),
                                                cc4.z + uu.z * (hh.z - cc4.z),
                                                cc4.w + uu.w * (hh.w - cc4.w));
                        *(float4*)(H + r * STH + c4) = nh;
                    }
                }
            }
            __syncthreads();
        } // cell
    } // t

    // ---- epilogue: logits = relu(hB) @ fc_w + fc_b; out[b] = max over nodes ----
    if (tid < RB) {
        float acc = fcb[0];
#pragma unroll
        for (int c = 0; c < HIDN; c++)
            acc += fmaxf(sm.hB[tid * STH + c], 0.f) * fcw[c];
        sm.Da[tid] = acc;
    }
    __syncthreads();
    if (tid < NB) {
        float mx = -3.4e38f;
#pragma unroll
        for (int n = 0; n < NNODE; n++)
            mx = fmaxf(mx, sm.Da[tid * NNODE + n]);
        out[bbase + tid] = mx;
    }
}

extern "C" void kernel_launch(void* const* d_in, const int* in_sizes, int n_in,
                              void* d_out, int out_size)
{
    (void)in_sizes; (void)n_in; (void)out_size;
    const size_t shbytes = sizeof(Smem);
    cudaFuncSetAttribute(dcrnn_kernel,
                         cudaFuncAttributeMaxDynamicSharedMemorySize,
                         (int)shbytes);
    dcrnn_kernel<<<NBLK, THREADS, shbytes>>>(
        (const float*)d_in[0],  (const float*)d_in[1],
        (const float*)d_in[2],  (const float*)d_in[3],
        (const float*)d_in[4],  (const float*)d_in[5],
        (const float*)d_in[6],  (const float*)d_in[7],
        (const float*)d_in[8],  (const float*)d_in[9],
        (const float*)d_in[10], (const float*)d_in[11],
        (float*)d_out);
}

// round 11
// speedup vs baseline: 1.0019x; 1.0019x over previous
#include <cuda_runtime.h>

#define NB      4
#define RB      72          // NB * 18 rows per CTA
#define THREADS 256
#define TSTEPS  128
#define NNODE   18
#define DIMX    32
#define HIDN    64
#define STF     132         // feature-buffer row stride (floats), padded
#define STH     68          // hidden-state row stride
#define STX     36          // x-tile row stride
#define NBLK    128         // grid: 512 / NB
#define STS2    24          // St2 row stride in float2

typedef unsigned long long u64;

// ---------------- packed f32x2 helpers ----------------
__device__ __forceinline__ u64 pk2(float a, float b) {
    u64 r;
    asm("mov.b64 %0, {%1, %2};" : "=l"(r)
        : "r"(__float_as_uint(a)), "r"(__float_as_uint(b)));
    return r;
}
__device__ __forceinline__ float2 up2(u64 v) {
    unsigned lo, hi;
    asm("mov.b64 {%0, %1}, %2;" : "=r"(lo), "=r"(hi) : "l"(v));
    return make_float2(__uint_as_float(lo), __uint_as_float(hi));
}
__device__ __forceinline__ void fma2(u64 &d, u64 a, u64 b) {
    asm("fma.rn.f32x2 %0, %1, %2, %0;" : "+l"(d) : "l"(a), "l"(b));
}
__device__ __forceinline__ void add2(u64 &d, u64 a) {
    asm("add.rn.f32x2 %0, %0, %1;" : "+l"(d) : "l"(a));
}

__device__ __forceinline__ float sigm(float v) {
    return 1.f / (1.f + __expf(-v));
}
__device__ __forceinline__ float tanh_(float v) {
    float e = __expf(2.f * v);
    return 1.f - 2.f / (e + 1.f);
}

// ---------------- shared memory layout ----------------
struct __align__(16) Smem {
    float2 St2[2][NNODE * STS2]; // transposed supports, duplicated pairs
    float X[RB * STX];          // x tile for current t
    float hA[RB * STH];
    float hB[RB * STH];
    float Z[RB * STF];          // concat input (gate Z; becomes cand Z in-place)
    float Da[RB * STF];         // Chebyshev x1 (aliases reduce scratch when dead)
    float Db[RB * STF];         // Chebyshev x2
    float OUT[RB * STF];        // gate output; only u-half (cols 64..127) used
};
// sizeof = 206688 B  (<= 227 KB dyn-smem limit, 1 CTA/SM)

// ---------------- spmm (4 cols/thread): dst = S @ src  (or 2*S@src - Zsub) ----
__device__ __forceinline__ void spmm4(const float2* __restrict__ St,
                                      const float* __restrict__ src,
                                      float* __restrict__ dst,
                                      const float* __restrict__ zsub,
                                      int CC, int rbase, int bloc, int nlo,
                                      int c0)
{
    if (c0 >= CC) return;
    const float* srcb = src + bloc * NNODE * STF + c0;
    u64 a[18];
#pragma unroll
    for (int i = 0; i < 18; i++) a[i] = 0;
#pragma unroll 1
    for (int mm = 0; mm < NNODE; mm++) {
        ulonglong2 z = *(const ulonglong2*)(srcb + mm * STF);
        const float2* sp = St + mm * STS2 + nlo;
        ulonglong2 p01 = *(const ulonglong2*)(sp);
        ulonglong2 p23 = *(const ulonglong2*)(sp + 2);
        ulonglong2 p45 = *(const ulonglong2*)(sp + 4);
        ulonglong2 p67 = *(const ulonglong2*)(sp + 6);
        u64        p8  = *(const u64*)(sp + 8);
        fma2(a[0],  p01.x, z.x); fma2(a[1],  p01.x, z.y);
        fma2(a[2],  p01.y, z.x); fma2(a[3],  p01.y, z.y);
        fma2(a[4],  p23.x, z.x); fma2(a[5],  p23.x, z.y);
        fma2(a[6],  p23.y, z.x); fma2(a[7],  p23.y, z.y);
        fma2(a[8],  p45.x, z.x); fma2(a[9],  p45.x, z.y);
        fma2(a[10], p45.y, z.x); fma2(a[11], p45.y, z.y);
        fma2(a[12], p67.x, z.x); fma2(a[13], p67.x, z.y);
        fma2(a[14], p67.y, z.x); fma2(a[15], p67.y, z.y);
        fma2(a[16], p8,    z.x); fma2(a[17], p8,    z.y);
    }
#pragma unroll
    for (int i = 0; i < 9; i++) {
        float2 q0 = up2(a[2 * i]), q1 = up2(a[2 * i + 1]);
        float4 o;
        if (zsub) {
            float4 zz = *(const float4*)(zsub + (rbase + i) * STF + c0);
            o = make_float4(2.f * q0.x - zz.x, 2.f * q0.y - zz.y,
                            2.f * q1.x - zz.z, 2.f * q1.y - zz.w);
        } else {
            o = make_float4(q0.x, q0.y, q1.x, q1.y);
        }
        *(float4*)(dst + (rbase + i) * STF + c0) = o;
    }
}

// ---------------- W loaders ----------------
__device__ __forceinline__ void ldwg(const float* p, ulonglong2 w[8]) {
#pragma unroll
    for (int kk = 0; kk < 4; kk++) {
        w[2 * kk]     = __ldg((const ulonglong2*)(p + kk * 128));
        w[2 * kk + 1] = __ldg((const ulonglong2*)(p + kk * 128 + 4));
    }
}
__device__ __forceinline__ void ldwc(const float* p, ulonglong2 w[4]) {
#pragma unroll
    for (int kk = 0; kk < 4; kk++)
        w[kk] = __ldg((const ulonglong2*)(p + kk * 64));
}

// gate GEMM k-slice: 9 rows x 8 cols per thread (16 fma2 per feat LDS.128)
template<int CC>
__device__ __forceinline__ void gemm_gate(const float* __restrict__ feat,
                                          const float* __restrict__ W,
                                          int kbeg, int c8, int rbase,
                                          u64 acc[36])
{
    constexpr int G = CC / 8;   // 4-k groups in this k-half
    const float* wp = W + (size_t)kbeg * 128 + c8;
    ulonglong2 wc[8], wn[8];
    ldwg(wp, wc);
#pragma unroll 2
    for (int g = 0; g < G; g++) {
        if (g + 1 < G) ldwg(wp + (size_t)(g + 1) * 512, wn);
        const float* fp = feat + rbase * STF + kbeg + 4 * g;
#pragma unroll
        for (int i = 0; i < 9; i++) {
            float4 f = *(const float4*)(fp + i * STF);
            u64 f0 = pk2(f.x, f.x), f1 = pk2(f.y, f.y);
            u64 f2 = pk2(f.z, f.z), f3 = pk2(f.w, f.w);
            fma2(acc[4 * i + 0], f0, wc[0].x); fma2(acc[4 * i + 1], f0, wc[0].y);
            fma2(acc[4 * i + 2], f0, wc[1].x); fma2(acc[4 * i + 3], f0, wc[1].y);
            fma2(acc[4 * i + 0], f1, wc[2].x); fma2(acc[4 * i + 1], f1, wc[2].y);
            fma2(acc[4 * i + 2], f1, wc[3].x); fma2(acc[4 * i + 3], f1, wc[3].y);
            fma2(acc[4 * i + 0], f2, wc[4].x); fma2(acc[4 * i + 1], f2, wc[4].y);
            fma2(acc[4 * i + 2], f2, wc[5].x); fma2(acc[4 * i + 3], f2, wc[5].y);
            fma2(acc[4 * i + 0], f3, wc[6].x); fma2(acc[4 * i + 1], f3, wc[6].y);
            fma2(acc[4 * i + 2], f3, wc[7].x); fma2(acc[4 * i + 3], f3, wc[7].y);
        }
#pragma unroll
        for (int q = 0; q < 8; q++) wc[q] = wn[q];
    }
}

// cand GEMM k-slice: 9 rows x 4 cols per thread
template<int CC>
__device__ __forceinline__ void gemm_cand(const float* __restrict__ feat,
                                          const float* __restrict__ W,
                                          int kbeg, int c4, int rbase,
                                          u64 acc[18])
{
    constexpr int G = CC / 8;
    const float* wp = W + (size_t)kbeg * 64 + c4;
    ulonglong2 wc[4], wn[4];
    ldwc(wp, wc);
#pragma unroll 2
    for (int g = 0; g < G; g++) {
        if (g + 1 < G) ldwc(wp + (size_t)(g + 1) * 256, wn);
        const float* fp = feat + rbase * STF + kbeg + 4 * g;
#pragma unroll
        for (int i = 0; i < 9; i++) {
            float4 f = *(const float4*)(fp + i * STF);
            fma2(acc[2 * i],     pk2(f.x, f.x), wc[0].x);
            fma2(acc[2 * i + 1], pk2(f.x, f.x), wc[0].y);
            fma2(acc[2 * i],     pk2(f.y, f.y), wc[1].x);
            fma2(acc[2 * i + 1], pk2(f.y, f.y), wc[1].y);
            fma2(acc[2 * i],     pk2(f.z, f.z), wc[2].x);
            fma2(acc[2 * i + 1], pk2(f.z, f.z), wc[2].y);
            fma2(acc[2 * i],     pk2(f.w, f.w), wc[3].x);
            fma2(acc[2 * i + 1], pk2(f.w, f.w), wc[3].y);
        }
#pragma unroll
        for (int q = 0; q < 4; q++) wc[q] = wn[q];
    }
}

// ---------------- main persistent kernel ----------------
__global__ void __launch_bounds__(THREADS, 1)
dcrnn_kernel(const float* __restrict__ x,   const float* __restrict__ sup,
             const float* __restrict__ wg0, const float* __restrict__ bg0,
             const float* __restrict__ wc0, const float* __restrict__ bc0,
             const float* __restrict__ wg1, const float* __restrict__ bg1,
             const float* __restrict__ wc1, const float* __restrict__ bc1,
             const float* __restrict__ fcw, const float* __restrict__ fcb,
             float* __restrict__ out)
{
    extern __shared__ char smraw[];
    Smem& sm = *reinterpret_cast<Smem*>(smraw);

    const int tid   = threadIdx.x;
    const int bbase = blockIdx.x * NB;
    const int rowg  = tid & 7;            // 8 row groups of 9 rows
    const int colg  = (tid >> 3) & 15;    // 16 col groups
    const int khalf = tid >> 7;           // k-slice half
    const int c8    = 8 * colg;           // gate col base
    const int c4    = 4 * colg;           // cand col base
    const int c0    = 4 * colg + 64 * khalf;  // spmm col base (covers 0..124)
    const int rbase = rowg * 9;
    const int bloc  = rowg >> 1;          // local batch of this thread's rows
    const int nlo   = (rowg & 1) ? 12 : 0; // St2 lane base

    u64* const scr = (u64*)sm.Da;         // reduce scratch aliases Da (dead then)

    // init: transpose + duplicate supports into St2
    for (int i = tid; i < 2 * NNODE * NNODE; i += THREADS) {
        int s = i / (NNODE * NNODE);
        int rem = i - s * NNODE * NNODE;
        int n = rem / NNODE;              // row of S
        int m = rem - n * NNODE;          // col of S
        float v = sup[i];
        int lane = (n < 9) ? n : (12 + n - 9);
        sm.St2[s][m * STS2 + lane] = make_float2(v, v);
    }
    for (int i = tid; i < RB * STH; i += THREADS) { sm.hA[i] = 0.f; sm.hB[i] = 0.f; }
    __syncthreads();

    for (int t = 0; t < TSTEPS; t++) {
        // ---- load x tile: X[r][0:32] = x[b, t, n, :] ----
        for (int j = tid; j < RB * 8; j += THREADS) {
            int r = j >> 3, d4 = j & 7;
            int b = bbase + r / NNODE;
            int n = r - NNODE * (r / NNODE);
            float4 v = *(const float4*)(x +
                (((size_t)b * TSTEPS + t) * NNODE + n) * DIMX + 4 * d4);
            *(float4*)(sm.X + r * STX + 4 * d4) = v;
        }
        __syncthreads();

        for (int cell = 0; cell < 2; cell++) {
            const int CC  = cell ? 128 : 96;
            const int CCH = CC >> 1;
            const int kbeg = khalf * CCH;
            const int hoff = cell ? HIDN : DIMX;   // offset of h-region in Z
            const float* WG = cell ? wg1 : wg0;
            const float* BG = cell ? bg1 : bg0;
            const float* WC = cell ? wc1 : wc0;
            const float* BC = cell ? bc1 : bc0;
            float* H = cell ? sm.hB : sm.hA;       // this cell's own state

            // ============ gate Z build: Z = [input | H] ============
            if (cell == 0) {
                for (int j = tid; j < RB * 24; j += THREADS) {
                    int r = j / 24, c = 4 * (j - 24 * r);
                    float4 v = (c < DIMX)
                        ? *(const float4*)(sm.X + r * STX + c)
                        : *(const float4*)(sm.hA + r * STH + (c - DIMX));
                    *(float4*)(sm.Z + r * STF + c) = v;
                }
            } else {
                for (int j = tid; j < RB * 32; j += THREADS) {
                    int r = j >> 5, c = 4 * (j & 31);
                    float4 v = (c < HIDN)
                        ? *(const float4*)(sm.hA + r * STH + c)
                        : *(const float4*)(sm.hB + r * STH + (c - HIDN));
                    *(float4*)(sm.Z + r * STF + c) = v;
                }
            }
            __syncthreads();

            // ============ GATE dconv + fused cand-Z build ============
            {
                u64 ga[36];
#pragma unroll
                for (int q = 0; q < 36; q++) ga[q] = 0;
#pragma unroll 1
                for (int m = 0; m < 5; m++) {
                    const float* feat;
                    if (m == 0) feat = sm.Z;
                    else {
                        int s = (m - 1) >> 1;
                        int second = (m - 1) & 1;
                        const float* src = second ? sm.Da : sm.Z;
                        float* dst = second ? sm.Db : sm.Da;
                        spmm4(sm.St2[s], src, dst,
                              second ? sm.Z : (const float*)0,
                              CC, rbase, bloc, nlo, c0);
                        __syncthreads();
                        feat = dst;
                    }
                    if (cell) gemm_gate<128>(feat, WG + (size_t)m * 128 * 128,
                                             kbeg, c8, rbase, ga);
                    else      gemm_gate<96> (feat, WG + (size_t)m * 96 * 128,
                                             kbeg, c8, rbase, ga);
                }
                __syncthreads();              // gemm done; Da/Db dead
                if (khalf) {
                    u64* s = scr + (size_t)(tid - 128) * 36;
#pragma unroll
                    for (int q = 0; q < 36; q++) s[q] = ga[q];
                }
                __syncthreads();
                if (!khalf) {
                    const u64* s = scr + (size_t)tid * 36;
#pragma unroll
                    for (int q = 0; q < 36; q++) add2(ga[q], s[q]);
                    float4 b0 = *(const float4*)(BG + c8);
                    float4 b1 = *(const float4*)(BG + c8 + 4);
                    if (c8 < HIDN) {
                        // r-part: write Z[r][hoff+c] = sigm(.)*H_prev[r][c]
#pragma unroll
                        for (int i = 0; i < 9; i++) {
                            int r = rbase + i;
                            float2 q0 = up2(ga[4 * i]),     q1 = up2(ga[4 * i + 1]);
                            float2 q2 = up2(ga[4 * i + 2]), q3 = up2(ga[4 * i + 3]);
                            float4 h0 = *(const float4*)(H + r * STH + c8);
                            float4 h1 = *(const float4*)(H + r * STH + c8 + 4);
                            float4 o0 = make_float4(sigm(q0.x + b0.x) * h0.x,
                                                    sigm(q0.y + b0.y) * h0.y,
                                                    sigm(q1.x + b0.z) * h0.z,
                                                    sigm(q1.y + b0.w) * h0.w);
                            float4 o1 = make_float4(sigm(q2.x + b1.x) * h1.x,
                                                    sigm(q2.y + b1.y) * h1.y,
                                                    sigm(q3.x + b1.z) * h1.z,
                                                    sigm(q3.y + b1.w) * h1.w);
                            *(float4*)(sm.Z + r * STF + hoff + c8)     = o0;
                            *(float4*)(sm.Z + r * STF + hoff + c8 + 4) = o1;
                        }
                    } else {
                        // u-part: store to OUT cols 64..127
#pragma unroll
                        for (int i = 0; i < 9; i++) {
                            int r = rbase + i;
                            float2 q0 = up2(ga[4 * i]),     q1 = up2(ga[4 * i + 1]);
                            float2 q2 = up2(ga[4 * i + 2]), q3 = up2(ga[4 * i + 3]);
                            float4 o0 = make_float4(sigm(q0.x + b0.x), sigm(q0.y + b0.y),
                                                    sigm(q1.x + b0.z), sigm(q1.y + b0.w));
                            float4 o1 = make_float4(sigm(q2.x + b1.x), sigm(q2.y + b1.y),
                                                    sigm(q3.x + b1.z), sigm(q3.y + b1.w));
                            *(float4*)(sm.OUT + r * STF + c8)     = o0;
                            *(float4*)(sm.OUT + r * STF + c8 + 4) = o1;
                        }
                    }
                }
                // Z low cols (input part) are already correct from gate Z build
            }
            __syncthreads();

            // ============ CANDIDATE dconv + fused GRU update ============
            {
                u64 ca[18];
#pragma unroll
                for (int q = 0; q < 18; q++) ca[q] = 0;
#pragma unroll 1
                for (int m = 0; m < 5; m++) {
                    const float* feat;
                    if (m == 0) feat = sm.Z;
                    else {
                        int s = (m - 1) >> 1;
                        int second = (m - 1) & 1;
                        const float* src = second ? sm.Da : sm.Z;
                        float* dst = second ? sm.Db : sm.Da;
                        spmm4(sm.St2[s], src, dst,
                              second ? sm.Z : (const float*)0,
                              CC, rbase, bloc, nlo, c0);
                        __syncthreads();
                        feat = dst;
                    }
                    if (cell) gemm_cand<128>(feat, WC + (size_t)m * 128 * 64,
                                             kbeg, c4, rbase, ca);
                    else      gemm_cand<96> (feat, WC + (size_t)m * 96 * 64,
                                             kbeg, c4, rbase, ca);
                }
                __syncthreads();
                if (khalf) {
                    u64* s = scr + (size_t)(tid - 128) * 18;
#pragma unroll
                    for (int q = 0; q < 18; q++) s[q] = ca[q];
                }
                __syncthreads();
                if (!khalf) {
                    const u64* s = scr + (size_t)tid * 18;
#pragma unroll
                    for (int q = 0; q < 18; q++) add2(ca[q], s[q]);
                    float4 bv = *(const float4*)(BC + c4);
#pragma unroll
                    for (int i = 0; i < 9; i++) {
                        int r = rbase + i;
                        float2 q0 = up2(ca[2 * i]), q1 = up2(ca[2 * i + 1]);
                        float4 cc4 = make_float4(tanh_(q0.x + bv.x), tanh_(q0.y + bv.y),
                                                 tanh_(q1.x + bv.z), tanh_(q1.y + bv.w));
                        float4 uu = *(const float4*)(sm.OUT + r * STF + HIDN + c4);
                        float4 hh = *(const float4*)(H + r * STH + c4);
                        float4 nh = make_float4(cc4.x + uu.x * (hh.x - cc4.x),
                                                cc4.y + uu.y * (hh.y - cc4.y),
                                                cc4.z + uu.z * (hh.z - cc4.z),
                                                cc4.w + uu.w * (hh.w - cc4.w));
                        *(float4*)(H + r * STH + c4) = nh;
                    }
                }
            }
            __syncthreads();
        } // cell
    } // t

    // ---- epilogue: logits = relu(hB) @ fc_w + fc_b; out[b] = max over nodes ----
    if (tid < RB) {
        float acc = fcb[0];
#pragma unroll
        for (int c = 0; c < HIDN; c++)
            acc += fmaxf(sm.hB[tid * STH + c], 0.f) * fcw[c];
        sm.Da[tid] = acc;
    }
    __syncthreads();
    if (tid < NB) {
        float mx = -3.4e38f;
#pragma unroll
        for (int n = 0; n < NNODE; n++)
            mx = fmaxf(mx, sm.Da[tid * NNODE + n]);
        out[bbase + tid] = mx;
    }
}

extern "C" void kernel_launch(void* const* d_in, const int* in_sizes, int n_in,
                              void* d_out, int out_size)
{
    (void)in_sizes; (void)n_in; (void)out_size;
    const size_t shbytes = sizeof(Smem);
    cudaFuncSetAttribute(dcrnn_kernel,
                         cudaFuncAttributeMaxDynamicSharedMemorySize,
                         (int)shbytes);
    dcrnn_kernel<<<NBLK, THREADS, shbytes>>>(
        (const float*)d_in[0],  (const float*)d_in[1],
        (const float*)d_in[2],  (const float*)d_in[3],
        (const float*)d_in[4],  (const float*)d_in[5],
        (const float*)d_in[6],  (const float*)d_in[7],
        (const float*)d_in[8],  (const float*)d_in[9],
        (const float*)d_in[10], (const float*)d_in[11],
        (float*)d_out);
}

// round 12
// speedup vs baseline: 1.0678x; 1.0657x over previous
#include <cuda_runtime.h>

#define NB      4
#define RB      72          // NB * 18 rows per CTA
#define THREADS 256
#define TSTEPS  128
#define NNODE   18
#define DIMX    32
#define HIDN    64
#define STF     132         // feature-buffer row stride (floats), padded
#define STH     68          // hidden-state row stride
#define NBLK    128         // grid: 512 / NB
#define STS2    24          // St2 row stride in float2

typedef unsigned long long u64;

// ---------------- packed f32x2 helpers ----------------
__device__ __forceinline__ u64 pk2(float a, float b) {
    u64 r;
    asm("mov.b64 %0, {%1, %2};" : "=l"(r)
        : "r"(__float_as_uint(a)), "r"(__float_as_uint(b)));
    return r;
}
__device__ __forceinline__ float2 up2(u64 v) {
    unsigned lo, hi;
    asm("mov.b64 {%0, %1}, %2;" : "=r"(lo), "=r"(hi) : "l"(v));
    return make_float2(__uint_as_float(lo), __uint_as_float(hi));
}
__device__ __forceinline__ void fma2(u64 &d, u64 a, u64 b) {
    asm("fma.rn.f32x2 %0, %1, %2, %0;" : "+l"(d) : "l"(a), "l"(b));
}
__device__ __forceinline__ void add2(u64 &d, u64 a) {
    asm("add.rn.f32x2 %0, %0, %1;" : "+l"(d) : "l"(a));
}

// ---------------- approx transcendentals (2 MUFU, no div.rn chain) ----------
__device__ __forceinline__ float ex2f(float x) {
    float r; asm("ex2.approx.ftz.f32 %0, %1;" : "=f"(r) : "f"(x)); return r;
}
__device__ __forceinline__ float rcpf(float x) {
    float r; asm("rcp.approx.ftz.f32 %0, %1;" : "=f"(r) : "f"(x)); return r;
}
__device__ __forceinline__ float sigm(float v) {
    // 1/(1+exp(-v)) = 1/(1+2^(-v*log2e))
    return rcpf(1.f + ex2f(-1.4426950408889634f * v));
}
__device__ __forceinline__ float tanh_(float v) {
    // 1 - 2/(exp(2v)+1),  exp(2v) = 2^(v*2*log2e)
    return 1.f - 2.f * rcpf(1.f + ex2f(2.8853900817779268f * v));
}

// ---------------- shared memory layout ----------------
struct __align__(16) Smem {
    float2 St2[2][NNODE * STS2]; // transposed supports, duplicated pairs
    float hA[RB * STH];
    float hB[RB * STH];
    float Z[RB * STF];          // concat input (gate Z; becomes cand Z in-place)
    float Da[RB * STF];         // Chebyshev x1 (aliases reduce scratch when dead)
    float Db[RB * STF];         // Chebyshev x2
    float OUT[RB * STF];        // gate output; only u-half (cols 64..127) used
};
// sizeof = 196320 B  (<= 227 KB dyn-smem limit, 1 CTA/SM)

// ---------------- spmm (4 cols/thread): dst = S @ src  (or 2*S@src - Zsub) ----
__device__ __forceinline__ void spmm4(const float2* __restrict__ St,
                                      const float* __restrict__ src,
                                      float* __restrict__ dst,
                                      const float* __restrict__ zsub,
                                      int CC, int rbase, int bloc, int nlo,
                                      int c0)
{
    if (c0 >= CC) return;
    const float* srcb = src + bloc * NNODE * STF + c0;
    u64 a[18];
#pragma unroll
    for (int i = 0; i < 18; i++) a[i] = 0;
    ulonglong2 z = *(const ulonglong2*)(srcb);   // depth-1 prefetch
#pragma unroll 1
    for (int mm = 0; mm < NNODE; mm++) {
        ulonglong2 zc = z;
        if (mm + 1 < NNODE) z = *(const ulonglong2*)(srcb + (mm + 1) * STF);
        const float2* sp = St + mm * STS2 + nlo;
        ulonglong2 p01 = *(const ulonglong2*)(sp);
        ulonglong2 p23 = *(const ulonglong2*)(sp + 2);
        ulonglong2 p45 = *(const ulonglong2*)(sp + 4);
        ulonglong2 p67 = *(const ulonglong2*)(sp + 6);
        u64        p8  = *(const u64*)(sp + 8);
        fma2(a[0],  p01.x, zc.x); fma2(a[1],  p01.x, zc.y);
        fma2(a[2],  p01.y, zc.x); fma2(a[3],  p01.y, zc.y);
        fma2(a[4],  p23.x, zc.x); fma2(a[5],  p23.x, zc.y);
        fma2(a[6],  p23.y, zc.x); fma2(a[7],  p23.y, zc.y);
        fma2(a[8],  p45.x, zc.x); fma2(a[9],  p45.x, zc.y);
        fma2(a[10], p45.y, zc.x); fma2(a[11], p45.y, zc.y);
        fma2(a[12], p67.x, zc.x); fma2(a[13], p67.x, zc.y);
        fma2(a[14], p67.y, zc.x); fma2(a[15], p67.y, zc.y);
        fma2(a[16], p8,    zc.x); fma2(a[17], p8,    zc.y);
    }
#pragma unroll
    for (int i = 0; i < 9; i++) {
        float2 q0 = up2(a[2 * i]), q1 = up2(a[2 * i + 1]);
        float4 o;
        if (zsub) {
            float4 zz = *(const float4*)(zsub + (rbase + i) * STF + c0);
            o = make_float4(2.f * q0.x - zz.x, 2.f * q0.y - zz.y,
                            2.f * q1.x - zz.z, 2.f * q1.y - zz.w);
        } else {
            o = make_float4(q0.x, q0.y, q1.x, q1.y);
        }
        *(float4*)(dst + (rbase + i) * STF + c0) = o;
    }
}

// ---------------- W loaders ----------------
__device__ __forceinline__ void ldwg(const float* p, ulonglong2 w[8]) {
#pragma unroll
    for (int kk = 0; kk < 4; kk++) {
        w[2 * kk]     = __ldg((const ulonglong2*)(p + kk * 128));
        w[2 * kk + 1] = __ldg((const ulonglong2*)(p + kk * 128 + 4));
    }
}
__device__ __forceinline__ void ldwc(const float* p, ulonglong2 w[4]) {
#pragma unroll
    for (int kk = 0; kk < 4; kk++)
        w[kk] = __ldg((const ulonglong2*)(p + kk * 64));
}

// gate GEMM k-slice: 9 rows x 8 cols per thread (16 fma2 per feat LDS.128)
template<int CC>
__device__ __forceinline__ void gemm_gate(const float* __restrict__ feat,
                                          const float* __restrict__ W,
                                          int kbeg, int c8, int rbase,
                                          u64 acc[36])
{
    constexpr int G = CC / 8;   // 4-k groups in this k-half
    const float* wp = W + (size_t)kbeg * 128 + c8;
    ulonglong2 wc[8], wn[8];
    ldwg(wp, wc);
#pragma unroll 2
    for (int g = 0; g < G; g++) {
        if (g + 1 < G) ldwg(wp + (size_t)(g + 1) * 512, wn);
        const float* fp = feat + rbase * STF + kbeg + 4 * g;
#pragma unroll
        for (int i = 0; i < 9; i++) {
            float4 f = *(const float4*)(fp + i * STF);
            u64 f0 = pk2(f.x, f.x), f1 = pk2(f.y, f.y);
            u64 f2 = pk2(f.z, f.z), f3 = pk2(f.w, f.w);
            fma2(acc[4 * i + 0], f0, wc[0].x); fma2(acc[4 * i + 1], f0, wc[0].y);
            fma2(acc[4 * i + 2], f0, wc[1].x); fma2(acc[4 * i + 3], f0, wc[1].y);
            fma2(acc[4 * i + 0], f1, wc[2].x); fma2(acc[4 * i + 1], f1, wc[2].y);
            fma2(acc[4 * i + 2], f1, wc[3].x); fma2(acc[4 * i + 3], f1, wc[3].y);
            fma2(acc[4 * i + 0], f2, wc[4].x); fma2(acc[4 * i + 1], f2, wc[4].y);
            fma2(acc[4 * i + 2], f2, wc[5].x); fma2(acc[4 * i + 3], f2, wc[5].y);
            fma2(acc[4 * i + 0], f3, wc[6].x); fma2(acc[4 * i + 1], f3, wc[6].y);
            fma2(acc[4 * i + 2], f3, wc[7].x); fma2(acc[4 * i + 3], f3, wc[7].y);
        }
#pragma unroll
        for (int q = 0; q < 8; q++) wc[q] = wn[q];
    }
}

// cand GEMM k-slice: 9 rows x 4 cols per thread
template<int CC>
__device__ __forceinline__ void gemm_cand(const float* __restrict__ feat,
                                          const float* __restrict__ W,
                                          int kbeg, int c4, int rbase,
                                          u64 acc[18])
{
    constexpr int G = CC / 8;
    const float* wp = W + (size_t)kbeg * 64 + c4;
    ulonglong2 wc[4], wn[4];
    ldwc(wp, wc);
#pragma unroll 2
    for (int g = 0; g < G; g++) {
        if (g + 1 < G) ldwc(wp + (size_t)(g + 1) * 256, wn);
        const float* fp = feat + rbase * STF + kbeg + 4 * g;
#pragma unroll
        for (int i = 0; i < 9; i++) {
            float4 f = *(const float4*)(fp + i * STF);
            fma2(acc[2 * i],     pk2(f.x, f.x), wc[0].x);
            fma2(acc[2 * i + 1], pk2(f.x, f.x), wc[0].y);
            fma2(acc[2 * i],     pk2(f.y, f.y), wc[1].x);
            fma2(acc[2 * i + 1], pk2(f.y, f.y), wc[1].y);
            fma2(acc[2 * i],     pk2(f.z, f.z), wc[2].x);
            fma2(acc[2 * i + 1], pk2(f.z, f.z), wc[2].y);
            fma2(acc[2 * i],     pk2(f.w, f.w), wc[3].x);
            fma2(acc[2 * i + 1], pk2(f.w, f.w), wc[3].y);
        }
#pragma unroll
        for (int q = 0; q < 4; q++) wc[q] = wn[q];
    }
}

// ---------------- main persistent kernel ----------------
__global__ void __launch_bounds__(THREADS, 1)
dcrnn_kernel(const float* __restrict__ x,   const float* __restrict__ sup,
             const float* __restrict__ wg0, const float* __restrict__ bg0,
             const float* __restrict__ wc0, const float* __restrict__ bc0,
             const float* __restrict__ wg1, const float* __restrict__ bg1,
             const float* __restrict__ wc1, const float* __restrict__ bc1,
             const float* __restrict__ fcw, const float* __restrict__ fcb,
             float* __restrict__ out)
{
    extern __shared__ char smraw[];
    Smem& sm = *reinterpret_cast<Smem*>(smraw);

    const int tid   = threadIdx.x;
    const int bbase = blockIdx.x * NB;
    const int rowg  = tid & 7;            // 8 row groups of 9 rows
    const int colg  = (tid >> 3) & 15;    // 16 col groups
    const int khalf = tid >> 7;           // k-slice half
    const int c8    = 8 * colg;           // gate col base
    const int c4    = 4 * colg;           // cand col base
    const int c0    = 4 * colg + 64 * khalf;  // spmm col base (covers 0..124)
    const int rbase = rowg * 9;
    const int bloc  = rowg >> 1;          // local batch of this thread's rows
    const int nlo   = (rowg & 1) ? 12 : 0; // St2 lane base

    u64* const scr = (u64*)sm.Da;         // reduce scratch aliases Da (dead then)

    // init: transpose + duplicate supports into St2
    for (int i = tid; i < 2 * NNODE * NNODE; i += THREADS) {
        int s = i / (NNODE * NNODE);
        int rem = i - s * NNODE * NNODE;
        int n = rem / NNODE;              // row of S
        int m = rem - n * NNODE;          // col of S
        float v = sup[i];
        int lane = (n < 9) ? n : (12 + n - 9);
        sm.St2[s][m * STS2 + lane] = make_float2(v, v);
    }
    for (int i = tid; i < RB * STH; i += THREADS) { sm.hA[i] = 0.f; sm.hB[i] = 0.f; }
    __syncthreads();

    for (int t = 0; t < TSTEPS; t++) {
        for (int cell = 0; cell < 2; cell++) {
            const int CC  = cell ? 128 : 96;
            const int CCH = CC >> 1;
            const int kbeg = khalf * CCH;
            const int hoff = cell ? HIDN : DIMX;   // offset of h-region in Z
            const float* WG = cell ? wg1 : wg0;
            const float* BG = cell ? bg1 : bg0;
            const float* WC = cell ? wc1 : wc0;
            const float* BC = cell ? bc1 : bc0;
            float* H = cell ? sm.hB : sm.hA;       // this cell's own state

            // ============ gate Z build: Z = [input | H] ============
            if (cell == 0) {
                // x loaded straight from gmem into Z (X staging buffer removed)
                for (int j = tid; j < RB * 24; j += THREADS) {
                    int r = j / 24, c = 4 * (j - 24 * r);
                    float4 v;
                    if (c < DIMX) {
                        int b = bbase + r / NNODE;
                        int n = r - NNODE * (r / NNODE);
                        v = *(const float4*)(x +
                            (((size_t)b * TSTEPS + t) * NNODE + n) * DIMX + c);
                    } else {
                        v = *(const float4*)(sm.hA + r * STH + (c - DIMX));
                    }
                    *(float4*)(sm.Z + r * STF + c) = v;
                }
            } else {
                for (int j = tid; j < RB * 32; j += THREADS) {
                    int r = j >> 5, c = 4 * (j & 31);
                    float4 v = (c < HIDN)
                        ? *(const float4*)(sm.hA + r * STH + c)
                        : *(const float4*)(sm.hB + r * STH + (c - HIDN));
                    *(float4*)(sm.Z + r * STF + c) = v;
                }
            }
            __syncthreads();

            // ============ GATE dconv + fused cand-Z build ============
            {
                u64 ga[36];
#pragma unroll
                for (int q = 0; q < 36; q++) ga[q] = 0;
#pragma unroll 1
                for (int m = 0; m < 5; m++) {
                    const float* feat;
                    if (m == 0) feat = sm.Z;
                    else {
                        int s = (m - 1) >> 1;
                        int second = (m - 1) & 1;
                        const float* src = second ? sm.Da : sm.Z;
                        float* dst = second ? sm.Db : sm.Da;
                        spmm4(sm.St2[s], src, dst,
                              second ? sm.Z : (const float*)0,
                              CC, rbase, bloc, nlo, c0);
                        __syncthreads();
                        feat = dst;
                    }
                    if (cell) gemm_gate<128>(feat, WG + (size_t)m * 128 * 128,
                                             kbeg, c8, rbase, ga);
                    else      gemm_gate<96> (feat, WG + (size_t)m * 96 * 128,
                                             kbeg, c8, rbase, ga);
                }
                __syncthreads();              // gemm done; Da/Db dead
                if (khalf) {
                    u64* s = scr + (size_t)(tid - 128) * 36;
#pragma unroll
                    for (int q = 0; q < 36; q++) s[q] = ga[q];
                }
                __syncthreads();
                if (!khalf) {
                    const u64* s = scr + (size_t)tid * 36;
#pragma unroll
                    for (int q = 0; q < 36; q++) add2(ga[q], s[q]);
                    float4 b0 = *(const float4*)(BG + c8);
                    float4 b1 = *(const float4*)(BG + c8 + 4);
                    if (c8 < HIDN) {
                        // r-part: write Z[r][hoff+c] = sigm(.)*H_prev[r][c]
#pragma unroll
                        for (int i = 0; i < 9; i++) {
                            int r = rbase + i;
                            float2 q0 = up2(ga[4 * i]),     q1 = up2(ga[4 * i + 1]);
                            float2 q2 = up2(ga[4 * i + 2]), q3 = up2(ga[4 * i + 3]);
                            float4 h0 = *(const float4*)(H + r * STH + c8);
                            float4 h1 = *(const float4*)(H + r * STH + c8 + 4);
                            float4 o0 = make_float4(sigm(q0.x + b0.x) * h0.x,
                                                    sigm(q0.y + b0.y) * h0.y,
                                                    sigm(q1.x + b0.z) * h0.z,
                                                    sigm(q1.y + b0.w) * h0.w);
                            float4 o1 = make_float4(sigm(q2.x + b1.x) * h1.x,
                                                    sigm(q2.y + b1.y) * h1.y,
                                                    sigm(q3.x + b1.z) * h1.z,
                                                    sigm(q3.y + b1.w) * h1.w);
                            *(float4*)(sm.Z + r * STF + hoff + c8)     = o0;
                            *(float4*)(sm.Z + r * STF + hoff + c8 + 4) = o1;
                        }
                    } else {
                        // u-part: store to OUT cols 64..127
#pragma unroll
                        for (int i = 0; i < 9; i++) {
                            int r = rbase + i;
                            float2 q0 = up2(ga[4 * i]),     q1 = up2(ga[4 * i + 1]);
                            float2 q2 = up2(ga[4 * i + 2]), q3 = up2(ga[4 * i + 3]);
                            float4 o0 = make_float4(sigm(q0.x + b0.x), sigm(q0.y + b0.y),
                                                    sigm(q1.x + b0.z), sigm(q1.y + b0.w));
                            float4 o1 = make_float4(sigm(q2.x + b1.x), sigm(q2.y + b1.y),
                                                    sigm(q3.x + b1.z), sigm(q3.y + b1.w));
                            *(float4*)(sm.OUT + r * STF + c8)     = o0;
                            *(float4*)(sm.OUT + r * STF + c8 + 4) = o1;
                        }
                    }
                }
                // Z low cols (input part) are already correct from gate Z build
            }
            __syncthreads();

            // ============ CANDIDATE dconv + fused GRU update ============
            {
                u64 ca[18];
#pragma unroll
                for (int q = 0; q < 18; q++) ca[q] = 0;
#pragma unroll 1
                for (int m = 0; m < 5; m++) {
                    const float* feat;
                    if (m == 0) feat = sm.Z;
                    else {
                        int s = (m - 1) >> 1;
                        int second = (m - 1) & 1;
                        const float* src = second ? sm.Da : sm.Z;
                        float* dst = second ? sm.Db : sm.Da;
                        spmm4(sm.St2[s], src, dst,
                              second ? sm.Z : (const float*)0,
                              CC, rbase, bloc, nlo, c0);
                        __syncthreads();
                        feat = dst;
                    }
                    if (cell) gemm_cand<128>(feat, WC + (size_t)m * 128 * 64,
                                             kbeg, c4, rbase, ca);
                    else      gemm_cand<96> (feat, WC + (size_t)m * 96 * 64,
                                             kbeg, c4, rbase, ca);
                }
                __syncthreads();
                if (khalf) {
                    u64* s = scr + (size_t)(tid - 128) * 18;
#pragma unroll
                    for (int q = 0; q < 18; q++) s[q] = ca[q];
                }
                __syncthreads();
                if (!khalf) {
                    const u64* s = scr + (size_t)tid * 18;
#pragma unroll
                    for (int q = 0; q < 18; q++) add2(ca[q], s[q]);
                    float4 bv = *(const float4*)(BC + c4);
#pragma unroll
                    for (int i = 0; i < 9; i++) {
                        int r = rbase + i;
                        float2 q0 = up2(ca[2 * i]), q1 = up2(ca[2 * i + 1]);
                        float4 cc4 = make_float4(tanh_(q0.x + bv.x), tanh_(q0.y + bv.y),
                                                 tanh_(q1.x + bv.z), tanh_(q1.y + bv.w));
                        float4 uu = *(const float4*)(sm.OUT + r * STF + HIDN + c4);
                        float4 hh = *(const float4*)(H + r * STH + c4);
                        float4 nh = make_float4(cc4.x + uu.x * (hh.x - cc4.x),
                                                cc4.y + uu.y * (hh.y - cc4.y),
                                                cc4.z + uu.z * (hh.z - cc4.z),
                                                cc4.w + uu.w * (hh.w - cc4.w));
                        *(float4*)(H + r * STH + c4) = nh;
                    }
                }
            }
            __syncthreads();
        } // cell
    } // t

    // ---- epilogue: logits = relu(hB) @ fc_w + fc_b; out[b] = max over nodes ----
    if (tid < RB) {
        float acc = fcb[0];
#pragma unroll
        for (int c = 0; c < HIDN; c++)
            acc += fmaxf(sm.hB[tid * STH + c], 0.f) * fcw[c];
        sm.Da[tid] = acc;
    }
    __syncthreads();
    if (tid < NB) {
        float mx = -3.4e38f;
#pragma unroll
        for (int n = 0; n < NNODE; n++)
            mx = fmaxf(mx, sm.Da[tid * NNODE + n]);
        out[bbase + tid] = mx;
    }
}

extern "C" void kernel_launch(void* const* d_in, const int* in_sizes, int n_in,
                              void* d_out, int out_size)
{
    (void)in_sizes; (void)n_in; (void)out_size;
    const size_t shbytes = sizeof(Smem);
    cudaFuncSetAttribute(dcrnn_kernel,
                         cudaFuncAttributeMaxDynamicSharedMemorySize,
                         (int)shbytes);
    dcrnn_kernel<<<NBLK, THREADS, shbytes>>>(
        (const float*)d_in[0],  (const float*)d_in[1],
        (const float*)d_in[2],  (const float*)d_in[3],
        (const float*)d_in[4],  (const float*)d_in[5],
        (const float*)d_in[6],  (const float*)d_in[7],
        (const float*)d_in[8],  (const float*)d_in[9],
        (const float*)d_in[10], (const float*)d_in[11],
        (float*)d_out);
}